// round 13
// baseline (speedup 1.0000x reference)
#include <cuda_runtime.h>
#include <cuda_bf16.h>
#include <cuda_fp16.h>
#include <math.h>
#include <stdint.h>

#define T_TOK 8192
#define D_DIM 2048
#define F_DIM 5632
#define E_EXP 8
#define R_RANK 16
#define GTOK 8

// ---------------- scratch (device globals; no allocations allowed) ----------
__device__ float g_base1[(size_t)T_TOK * F_DIM];
__device__ float g_base3[(size_t)T_TOK * F_DIM];
__device__ float g_la1 [T_TOK * 2 * R_RANK];
__device__ float g_la3 [T_TOK * 2 * R_RANK];
__device__ float g_la2c[T_TOK * 2 * R_RANK];
__device__ float g_coef[T_TOK * 2];
__device__ int   g_sel [T_TOK * 2];

// fp16 operands
__device__ __half g_xh  [(size_t)T_TOK * D_DIM];
__device__ __half g_w1h [(size_t)F_DIM * D_DIM];
__device__ __half g_w3h [(size_t)F_DIM * D_DIM];
__device__ __half g_w2h [(size_t)D_DIM * F_DIM];
__device__ __half g_gch [(size_t)T_TOK * F_DIM];
// fp16 LoRA weights; A2 stored transposed [e][f][r]
__device__ __half g_a1h [E_EXP * R_RANK * D_DIM];
__device__ __half g_a3h [E_EXP * R_RANK * D_DIM];
__device__ __half g_b1h [E_EXP * F_DIM * R_RANK];
__device__ __half g_b3h [E_EXP * F_DIM * R_RANK];
__device__ __half g_a2t [E_EXP * F_DIM * R_RANK];
__device__ __half g_b2h [E_EXP * D_DIM * R_RANK];

// =================== PTX helpers (sm_80-compatible only) ====================
__device__ __forceinline__ uint32_t smem_u32(const void* p) {
    uint32_t a;
    asm("{ .reg .u64 t; cvta.to.shared.u64 t, %1; cvt.u32.u64 %0, t; }"
        : "=r"(a) : "l"(p));
    return a;
}
__device__ __forceinline__ void cp16(uint32_t dst, const void* src) {
    asm volatile("cp.async.cg.shared.global [%0], [%1], 16;" :: "r"(dst), "l"(src));
}
#define CP_COMMIT() asm volatile("cp.async.commit_group;" ::: "memory")
#define CP_WAIT(n)  asm volatile("cp.async.wait_group %0;" :: "n"(n) : "memory")

__device__ __forceinline__ void ldsm4(uint32_t* r, uint32_t addr) {
    asm volatile("ldmatrix.sync.aligned.m8n8.x4.shared.b16 {%0,%1,%2,%3}, [%4];"
        : "=r"(r[0]), "=r"(r[1]), "=r"(r[2]), "=r"(r[3]) : "r"(addr));
}
__device__ __forceinline__ void mma_f16(float* c, const uint32_t* a,
                                        uint32_t b0, uint32_t b1) {
    asm volatile(
        "mma.sync.aligned.m16n8k16.row.col.f32.f16.f16.f32 "
        "{%0,%1,%2,%3}, {%4,%5,%6,%7}, {%8,%9}, {%0,%1,%2,%3};"
        : "+f"(c[0]), "+f"(c[1]), "+f"(c[2]), "+f"(c[3])
        : "r"(a[0]), "r"(a[1]), "r"(a[2]), "r"(a[3]), "r"(b0), "r"(b1));
}

// unpack uint4 (8 fp16) to 8 floats
__device__ __forceinline__ void unpack8(uint4 u, float* f) {
    float2 v;
    v = __half22float2(*(__half2*)&u.x); f[0] = v.x; f[1] = v.y;
    v = __half22float2(((__half2*)&u.x)[1]); f[2] = v.x; f[3] = v.y;
    v = __half22float2(*(__half2*)&u.z); f[4] = v.x; f[5] = v.y;
    v = __half22float2(((__half2*)&u.z)[1]); f[6] = v.x; f[7] = v.y;
}

// fp16 row of 16 (32B = two uint4 loads) dotted with fp32 vector (fp32 accum)
__device__ __forceinline__ float dot16h(const __half* w, const float* s) {
    uint4 u0 = *(const uint4*)(w);
    uint4 u1 = *(const uint4*)(w + 8);
    float a[8], b[8];
    unpack8(u0, a); unpack8(u1, b);
    float d = 0.f;
#pragma unroll
    for (int i = 0; i < 8; i++) d += s[i] * a[i] + s[8 + i] * b[i];
    return d;
}

// fp16 row of 16 dotted with half2[8] vector, fp16 accumulation (fast path)
__device__ __forceinline__ float dot16hh(const __half* w, const __half2* s) {
    uint4 u0 = *(const uint4*)(w);
    uint4 u1 = *(const uint4*)(w + 8);
    const __half2* wh0 = (const __half2*)&u0;
    const __half2* wh1 = (const __half2*)&u1;
    __half2 acc = __hmul2(wh0[0], s[0]);
#pragma unroll
    for (int i = 1; i < 4; i++) acc = __hfma2(wh0[i], s[i], acc);
#pragma unroll
    for (int i = 0; i < 4; i++) acc = __hfma2(wh1[i], s[4 + i], acc);
    return __low2float(acc) + __high2float(acc);
}

// =================== fp16 GEMM via mma.sync (128x256 tile) ==================
// C[M,N] = Ah[M,K] @ Bh[N,K]^T.  BM=128, BN=256, BK=64, 256 threads,
// 8 warps in 2(M) x 4(N) grid of 64x64 warp tiles.  2-stage cp.async.
#define ST_AH 0
#define ST_BH 16384                 // A: 128 rows x 128B
#define STAGE_SZ 49152              // + B: 256 rows x 128B
#define GEMM_SMEM (2 * STAGE_SZ)    // 96 KB

__device__ __forceinline__ uint32_t sw_off(int row, int c) {
    return (uint32_t)((row << 7) + ((c ^ (row & 7)) << 4));
}

// copy "rows" K-major rows of 64 fp16 (128B); rows*8 chunks over 256 threads
__device__ __forceinline__ void copy_rows(uint32_t dst, const __half* src,
                                          int ldk, int tid, int nit) {
    for (int it = 0; it < nit; it++) {
        int idx = tid + it * 256;
        int row = idx >> 3, c = idx & 7;
        cp16(dst + sw_off(row, c), src + (size_t)row * ldk + c * 8);
    }
}

__device__ __forceinline__ void ld_frag16(uint32_t arr, int baserow, int kstep,
                                          int lane, uint32_t* r) {
    int tile = lane >> 3, rin = lane & 7;
    int row = baserow + ((tile & 1) << 3) + rin;
    int chunk = (kstep << 1) + (tile >> 1);
    ldsm4(r, arr + sw_off(row, chunk));
}

// core GEMM body (one 128x256 output tile)
__device__ __forceinline__ void gemm_body(const __half* gAh, const __half* gBh,
                                          float* C, int N, int K,
                                          int bm, int bn, char* smem) {
    uint32_t sb = smem_u32(smem);
    const int tid = threadIdx.x, lane = tid & 31, wid = tid >> 5;
    const int warp_m = (wid & 1) * 64, warp_n = (wid >> 1) * 64;
    const int niter = K / 64;

    float acc[4][8][4];
#pragma unroll
    for (int i = 0; i < 4; i++)
#pragma unroll
        for (int j = 0; j < 8; j++)
#pragma unroll
            for (int v = 0; v < 4; v++) acc[i][j][v] = 0.f;

    {
        uint32_t st = sb;
        copy_rows(st + ST_AH, gAh, K, tid, 4);
        copy_rows(st + ST_BH, gBh, K, tid, 8);
        CP_COMMIT();
    }

    for (int i = 0; i < niter; i++) {
        uint32_t st = sb + (uint32_t)(i & 1) * STAGE_SZ;
        if (i + 1 < niter) {
            uint32_t stn = sb + (uint32_t)((i + 1) & 1) * STAGE_SZ;
            int k0 = (i + 1) * 64;
            copy_rows(stn + ST_AH, gAh + k0, K, tid, 4);
            copy_rows(stn + ST_BH, gBh + k0, K, tid, 8);
            CP_COMMIT();
            CP_WAIT(1);
        } else {
            CP_WAIT(0);
        }
        __syncthreads();

#pragma unroll
        for (int ks = 0; ks < 4; ks++) {
            uint32_t ah[4][4], bh[4][4];
#pragma unroll
            for (int mt = 0; mt < 4; mt++)
                ld_frag16(st + ST_AH, warp_m + mt * 16, ks, lane, ah[mt]);
#pragma unroll
            for (int ng = 0; ng < 4; ng++)
                ld_frag16(st + ST_BH, warp_n + ng * 16, ks, lane, bh[ng]);
#pragma unroll
            for (int mt = 0; mt < 4; mt++) {
#pragma unroll
                for (int nt = 0; nt < 8; nt++) {
                    int ng = nt >> 1, p = nt & 1;
                    mma_f16(acc[mt][nt], ah[mt], bh[ng][p], bh[ng][2 + p]);
                }
            }
        }
        __syncthreads();
    }

#pragma unroll
    for (int mt = 0; mt < 4; mt++) {
        int row = bm + warp_m + mt * 16 + (lane >> 2);
#pragma unroll
        for (int nt = 0; nt < 8; nt++) {
            int col = bn + warp_n + nt * 8 + (lane & 3) * 2;
            float* p0 = C + (size_t)row * N + col;
            float* p1 = C + (size_t)(row + 8) * N + col;
            *(float2*)p0 = make_float2(acc[mt][nt][0], acc[mt][nt][1]);
            *(float2*)p1 = make_float2(acc[mt][nt][2], acc[mt][nt][3]);
        }
    }
}

// single GEMM (down-projection)
__global__ void __launch_bounds__(256, 1)
gemm_mma_f16(const __half* __restrict__ Ah, const __half* __restrict__ Bh,
             float* __restrict__ C, int M, int N, int K) {
    extern __shared__ char smem[];
    int bm = blockIdx.y * 128, bn = blockIdx.x * 256;
    gemm_body(Ah + (size_t)bm * K, Bh + (size_t)bn * K, C, N, K, bm, bn, smem);
}

// dual up-projection GEMM: blockIdx.z selects (W1 -> base1) or (W3 -> base3)
__global__ void __launch_bounds__(256, 1)
gemm_mma_f16_up(const __half* __restrict__ Ah,
                const __half* __restrict__ B1h, const __half* __restrict__ B3h,
                float* __restrict__ C1, float* __restrict__ C3,
                int N, int K) {
    extern __shared__ char smem[];
    const __half* Bh = blockIdx.z ? B3h : B1h;
    float* C = blockIdx.z ? C3 : C1;
    int bm = blockIdx.y * 128, bn = blockIdx.x * 256;
    gemm_body(Ah + (size_t)bm * K, Bh + (size_t)bn * K, C, N, K, bm, bn, smem);
}

// =================== fp32 -> fp16 conversions ===============================
__global__ void split1_kernel(const float* __restrict__ in,
                              __half* __restrict__ hi, int n4) {
    int i = blockIdx.x * blockDim.x + threadIdx.x;
    if (i >= n4) return;
    float4 v = *(const float4*)(in + (size_t)i * 4);
    __half* hp = hi + (size_t)i * 4;
    *(__half2*)(hp)     = __half2(__float2half(v.x), __float2half(v.y));
    *(__half2*)(hp + 2) = __half2(__float2half(v.z), __float2half(v.w));
}

// A2[e][r][f] -> a2t[e][f][r] fp16
__global__ void a2t_kernel(const float* __restrict__ A2) {
    int i = blockIdx.x * blockDim.x + threadIdx.x;
    if (i >= E_EXP * F_DIM * R_RANK) return;
    int r = i & (R_RANK - 1);
    int f = (i / R_RANK) % F_DIM;
    int e = i / (R_RANK * F_DIM);
    g_a2t[i] = __float2half(A2[((size_t)e * R_RANK + r) * F_DIM + f]);
}

// ---------------- router ----------------------------------------------------
__global__ void router_kernel(const float* __restrict__ x,
                              const float* __restrict__ gw,
                              float* __restrict__ logits_out, int write_logits) {
    int t    = blockIdx.x * (blockDim.x >> 5) + (threadIdx.x >> 5);
    int lane = threadIdx.x & 31;
    if (t >= T_TOK) return;
    const float* h = x + (size_t)t * D_DIM;
    float acc[E_EXP];
#pragma unroll
    for (int e = 0; e < E_EXP; e++) acc[e] = 0.f;
    for (int d = lane * 4; d < D_DIM; d += 128) {
        float4 hv = *(const float4*)(h + d);
#pragma unroll
        for (int e = 0; e < E_EXP; e++) {
            float4 gv = *(const float4*)(gw + (size_t)e * D_DIM + d);
            acc[e] += hv.x * gv.x + hv.y * gv.y + hv.z * gv.z + hv.w * gv.w;
        }
    }
#pragma unroll
    for (int e = 0; e < E_EXP; e++) {
#pragma unroll
        for (int o = 16; o > 0; o >>= 1)
            acc[e] += __shfl_xor_sync(0xffffffffu, acc[e], o);
    }
    if (lane == 0) {
        if (write_logits) {
#pragma unroll
            for (int e = 0; e < E_EXP; e++)
                logits_out[(size_t)t * E_EXP + e] = acc[e];
        }
        float m = acc[0];
#pragma unroll
        for (int e = 1; e < E_EXP; e++) m = fmaxf(m, acc[e]);
        float p[E_EXP]; float s = 0.f;
#pragma unroll
        for (int e = 0; e < E_EXP; e++) { p[e] = expf(acc[e] - m); s += p[e]; }
        float invs = 1.f / s;
#pragma unroll
        for (int e = 0; e < E_EXP; e++) p[e] *= invs;
        int i0 = 0; float v0 = p[0];
#pragma unroll
        for (int e = 1; e < E_EXP; e++) if (p[e] > v0) { v0 = p[e]; i0 = e; }
        int i1 = -1; float v1 = -1.f;
#pragma unroll
        for (int e = 0; e < E_EXP; e++) {
            if (e == i0) continue;
            if (p[e] > v1) { v1 = p[e]; i1 = e; }
        }
        float inv = 1.f / (v0 + v1);
        g_sel [t * 2 + 0] = i0;  g_sel [t * 2 + 1] = i1;
        g_coef[t * 2 + 0] = v0 * inv;
        g_coef[t * 2 + 1] = v1 * inv;
    }
}

// ---------------- per-pair lora-A projections (all-fp16 reads) --------------
__global__ void loraA_kernel() {
    int p    = blockIdx.x * (blockDim.x >> 5) + (threadIdx.x >> 5);
    int lane = threadIdx.x & 31;
    if (p >= T_TOK * 2) return;
    int t = p >> 1;
    int e = g_sel[p];
    const __half* h  = g_xh  + (size_t)t * D_DIM;
    const __half* a1 = g_a1h + (size_t)e * R_RANK * D_DIM;
    const __half* a3 = g_a3h + (size_t)e * R_RANK * D_DIM;
    float acc1[R_RANK], acc3[R_RANK];
#pragma unroll
    for (int r = 0; r < R_RANK; r++) { acc1[r] = 0.f; acc3[r] = 0.f; }
    for (int d = lane * 8; d < D_DIM; d += 256) {
        float hv[8];
        unpack8(*(const uint4*)(h + d), hv);
#pragma unroll
        for (int r = 0; r < R_RANK; r++) {
            float av[8], cv[8];
            unpack8(*(const uint4*)(a1 + (size_t)r * D_DIM + d), av);
            unpack8(*(const uint4*)(a3 + (size_t)r * D_DIM + d), cv);
#pragma unroll
            for (int j = 0; j < 8; j++) {
                acc1[r] += hv[j] * av[j];
                acc3[r] += hv[j] * cv[j];
            }
        }
    }
#pragma unroll
    for (int r = 0; r < R_RANK; r++) {
#pragma unroll
        for (int o = 16; o > 0; o >>= 1) {
            acc1[r] += __shfl_xor_sync(0xffffffffu, acc1[r], o);
            acc3[r] += __shfl_xor_sync(0xffffffffu, acc3[r], o);
        }
    }
    if (lane == 0) {
#pragma unroll
        for (int r = 0; r < R_RANK; r++) {
            g_la1[p * R_RANK + r] = acc1[r];
            g_la3[p * R_RANK + r] = acc3[r];
        }
    }
}

// ---------------- fused gate: 8 tokens/CTA, 128-f chunks, L1 reuse ----------
__global__ void __launch_bounds__(128)
gate_kernel() {
    const int t0 = blockIdx.x * GTOK;
    const int tid = threadIdx.x;
    const int lane = tid & 31, wid = tid >> 5;
    __shared__ __half2 s_la1h[GTOK][2][8];
    __shared__ __half2 s_la3h[GTOK][2][8];
    __shared__ float s_coef[GTOK][2];
    __shared__ int   s_sel [GTOK][2];
    __shared__ float s_la2w[4][GTOK][32];

    {
        int tt = tid >> 4, rest = tid & 15;
        int slot = rest >> 3, rp = rest & 7;
        int base = (t0 + tt) * 32 + slot * 16 + rp * 2;
        s_la1h[tt][slot][rp] = __floats2half2_rn(g_la1[base], g_la1[base + 1]);
        s_la3h[tt][slot][rp] = __floats2half2_rn(g_la3[base], g_la3[base + 1]);
    }
    if (tid < GTOK * 2) {
        s_coef[tid >> 1][tid & 1] = g_coef[t0 * 2 + tid];
        s_sel [tid >> 1][tid & 1] = g_sel [t0 * 2 + tid];
    }
    for (int i = tid; i < 4 * GTOK * 32; i += 128)
        ((float*)s_la2w)[i] = 0.f;
    __syncthreads();

    const int rsel = lane & 15;
    for (int c0 = 0; c0 < F_DIM; c0 += 128) {
        const int f = c0 + tid;
        const int fbase = c0 + wid * 32;
#pragma unroll 1
        for (int tt = 0; tt < GTOK; tt++) {
            const int t = t0 + tt;
            const int e0 = s_sel[tt][0], e1 = s_sel[tt][1];
            const float cc0 = s_coef[tt][0], cc1 = s_coef[tt][1];
            float b1v = g_base1[(size_t)t * F_DIM + f];
            float b3v = g_base3[(size_t)t * F_DIM + f];
            float d10 = dot16hh(g_b1h + ((size_t)e0 * F_DIM + f) * R_RANK, s_la1h[tt][0]);
            float d11 = dot16hh(g_b1h + ((size_t)e1 * F_DIM + f) * R_RANK, s_la1h[tt][1]);
            float d30 = dot16hh(g_b3h + ((size_t)e0 * F_DIM + f) * R_RANK, s_la3h[tt][0]);
            float d31 = dot16hh(g_b3h + ((size_t)e1 * F_DIM + f) * R_RANK, s_la3h[tt][1]);
            float u10 = b1v + d10, u30 = b3v + d30;
            float u11 = b1v + d11, u31 = b3v + d31;
            float g0 = (u10 / (1.f + expf(-u10))) * u30;
            float g1 = (u11 / (1.f + expf(-u11))) * u31;
            g_gch[(size_t)t * F_DIM + f] = __float2half(cc0 * g0 + cc1 * g1);
            const int eM = (lane < 16) ? e0 : e1;
            const __half* arow = g_a2t + (size_t)eM * F_DIM * R_RANK + rsel;
            float p = 0.f;
#pragma unroll
            for (int s = 0; s < 32; s++) {
                float g0b = __shfl_sync(0xffffffffu, g0, s);
                float g1b = __shfl_sync(0xffffffffu, g1, s);
                float gb = (lane < 16) ? g0b : g1b;
                float av = __half2float(arow[(size_t)(fbase + s) * R_RANK]);
                p += gb * av;
            }
            s_la2w[wid][tt][lane] += p;
        }
    }
    __syncthreads();
    for (int i = tid; i < GTOK * 32; i += 128) {
        int tt = i >> 5, q = i & 31;
        float v = s_la2w[0][tt][q] + s_la2w[1][tt][q] + s_la2w[2][tt][q] + s_la2w[3][tt][q];
        float c = (q < 16) ? s_coef[tt][0] : s_coef[tt][1];
        g_la2c[(t0 + tt) * 32 + q] = v * c;
    }
}

// ---------------- out += sum_k la2c[p_k] @ B2[e_k]^T (fp16 B2, 16B loads) ----
__global__ void lora2_out_kernel(float* __restrict__ out) {
    int t   = blockIdx.x;
    int tid = threadIdx.x;
    __shared__ float s_l2[32];
    if (tid < 32) s_l2[tid] = g_la2c[t * 32 + tid];
    __syncthreads();
    int e0 = g_sel[t * 2], e1 = g_sel[t * 2 + 1];
    const __half* b2e0 = g_b2h + (size_t)e0 * D_DIM * R_RANK;
    const __half* b2e1 = g_b2h + (size_t)e1 * D_DIM * R_RANK;
    for (int d = tid; d < D_DIM; d += 256) {
        float s = dot16h(b2e0 + (size_t)d * R_RANK, s_l2)
                + dot16h(b2e1 + (size_t)d * R_RANK, s_l2 + 16);
        out[(size_t)t * D_DIM + d] += s;
    }
}

// ---------------- launch ----------------------------------------------------
extern "C" void kernel_launch(void* const* d_in, const int* in_sizes, int n_in,
                              void* d_out, int out_size) {
    (void)in_sizes; (void)n_in;
    const float* x  = (const float*)d_in[0];
    const float* gw = (const float*)d_in[1];
    const float* W1 = (const float*)d_in[2];
    const float* W3 = (const float*)d_in[3];
    const float* W2 = (const float*)d_in[4];
    const float* A1 = (const float*)d_in[5];
    const float* B1 = (const float*)d_in[6];
    const float* A3 = (const float*)d_in[7];
    const float* B3 = (const float*)d_in[8];
    const float* A2 = (const float*)d_in[9];
    const float* B2 = (const float*)d_in[10];
    float* out = (float*)d_out;

    int write_logits = (out_size >= T_TOK * D_DIM + T_TOK * E_EXP) ? 1 : 0;
    float* logits = out + (size_t)T_TOK * D_DIM;

    float *base1, *base3;
    __half *xh, *w1h, *w3h, *w2h, *gch;
    __half *a1h, *a3h, *b1h, *b3h, *b2h;
    cudaGetSymbolAddress((void**)&base1, g_base1);
    cudaGetSymbolAddress((void**)&base3, g_base3);
    cudaGetSymbolAddress((void**)&xh,   g_xh);
    cudaGetSymbolAddress((void**)&w1h,  g_w1h);
    cudaGetSymbolAddress((void**)&w3h,  g_w3h);
    cudaGetSymbolAddress((void**)&w2h,  g_w2h);
    cudaGetSymbolAddress((void**)&gch,  g_gch);
    cudaGetSymbolAddress((void**)&a1h,  g_a1h);
    cudaGetSymbolAddress((void**)&a3h,  g_a3h);
    cudaGetSymbolAddress((void**)&b1h,  g_b1h);
    cudaGetSymbolAddress((void**)&b3h,  g_b3h);
    cudaGetSymbolAddress((void**)&b2h,  g_b2h);

    cudaFuncSetAttribute(gemm_mma_f16,
                         cudaFuncAttributeMaxDynamicSharedMemorySize, GEMM_SMEM);
    cudaFuncSetAttribute(gemm_mma_f16_up,
                         cudaFuncAttributeMaxDynamicSharedMemorySize, GEMM_SMEM);

    // 1. routing (writes router_logits output)
    router_kernel<<<T_TOK / 8, 256>>>(x, gw, logits, write_logits);

    // 2. fp16 conversions (big operands + all LoRA weights; A2 transposed)
    {
        int n4;
        n4 = T_TOK * D_DIM / 4;          split1_kernel<<<(n4 + 255) / 256, 256>>>(x,  xh,  n4);
        n4 = F_DIM * D_DIM / 4;          split1_kernel<<<(n4 + 255) / 256, 256>>>(W1, w1h, n4);
        n4 = F_DIM * D_DIM / 4;          split1_kernel<<<(n4 + 255) / 256, 256>>>(W3, w3h, n4);
        n4 = D_DIM * F_DIM / 4;          split1_kernel<<<(n4 + 255) / 256, 256>>>(W2, w2h, n4);
        n4 = E_EXP * R_RANK * D_DIM / 4; split1_kernel<<<(n4 + 255) / 256, 256>>>(A1, a1h, n4);
        n4 = E_EXP * R_RANK * D_DIM / 4; split1_kernel<<<(n4 + 255) / 256, 256>>>(A3, a3h, n4);
        n4 = E_EXP * F_DIM * R_RANK / 4; split1_kernel<<<(n4 + 255) / 256, 256>>>(B1, b1h, n4);
        n4 = E_EXP * F_DIM * R_RANK / 4; split1_kernel<<<(n4 + 255) / 256, 256>>>(B3, b3h, n4);
        n4 = E_EXP * D_DIM * R_RANK / 4; split1_kernel<<<(n4 + 255) / 256, 256>>>(B2, b2h, n4);
        int nt = E_EXP * F_DIM * R_RANK;
        a2t_kernel<<<(nt + 255) / 256, 256>>>(A2);
    }

    // 3. per-pair lora-A projections (fp16 x + fp16 A)
    loraA_kernel<<<(T_TOK * 2) / 4, 128>>>();

    // 4. base projections: one merged launch (z = 0: W1->base1, z = 1: W3->base3)
    {
        dim3 gUp(F_DIM / 256, T_TOK / 128, 2);
        gemm_mma_f16_up<<<gUp, 256, GEMM_SMEM>>>(xh, w1h, w3h, base1, base3,
                                                 F_DIM, D_DIM);
    }

    // 5. fused SwiGLU gate (token-grouped) + combine + g@A2^T
    gate_kernel<<<T_TOK / GTOK, 128>>>();

    // 6. down projection: out = gc @ W2^T
    {
        dim3 gDn(D_DIM / 256, T_TOK / 128);
        gemm_mma_f16<<<gDn, 256, GEMM_SMEM>>>(gch, w2h, out, T_TOK, D_DIM, F_DIM);
    }

    // 7. rank-16 lora-2 epilogue
    lora2_out_kernel<<<T_TOK, 256>>>(out);
}

// round 17
// speedup vs baseline: 1.0829x; 1.0829x over previous
#include <cuda_runtime.h>
#include <cuda_bf16.h>
#include <cuda_fp16.h>
#include <math.h>
#include <stdint.h>

#define T_TOK 8192
#define D_DIM 2048
#define F_DIM 5632
#define E_EXP 8
#define R_RANK 16
#define GTOK 8
#define LA_N 256   // 8 experts * (16 la1 + 16 la3)

// ---------------- scratch (device globals; no allocations allowed) ----------
__device__ float g_base1[(size_t)T_TOK * F_DIM];
__device__ float g_base3[(size_t)T_TOK * F_DIM];
__device__ float g_laall[(size_t)T_TOK * LA_N];   // h @ [A1|A3 all experts]^T
__device__ float g_la2c[T_TOK * 2 * R_RANK];
__device__ float g_coef[T_TOK * 2];
__device__ int   g_sel [T_TOK * 2];

// fp16 operands
__device__ __half g_xh  [(size_t)T_TOK * D_DIM];
__device__ __half g_w1h [(size_t)F_DIM * D_DIM];
__device__ __half g_w3h [(size_t)F_DIM * D_DIM];
__device__ __half g_w2h [(size_t)D_DIM * F_DIM];
__device__ __half g_gch [(size_t)T_TOK * F_DIM];
__device__ __half g_lapk[LA_N * D_DIM];           // packed [A1|A3] fp16
// fp16 LoRA weights; A2 stored transposed [e][f][r]
__device__ __half g_b1h [E_EXP * F_DIM * R_RANK];
__device__ __half g_b3h [E_EXP * F_DIM * R_RANK];
__device__ __half g_a2t [E_EXP * F_DIM * R_RANK];
__device__ __half g_b2h [E_EXP * D_DIM * R_RANK];

// =================== PTX helpers (sm_80-compatible only) ====================
__device__ __forceinline__ uint32_t smem_u32(const void* p) {
    uint32_t a;
    asm("{ .reg .u64 t; cvta.to.shared.u64 t, %1; cvt.u32.u64 %0, t; }"
        : "=r"(a) : "l"(p));
    return a;
}
__device__ __forceinline__ void cp16(uint32_t dst, const void* src) {
    asm volatile("cp.async.cg.shared.global [%0], [%1], 16;" :: "r"(dst), "l"(src));
}
#define CP_COMMIT() asm volatile("cp.async.commit_group;" ::: "memory")
#define CP_WAIT(n)  asm volatile("cp.async.wait_group %0;" :: "n"(n) : "memory")

__device__ __forceinline__ void ldsm4(uint32_t* r, uint32_t addr) {
    asm volatile("ldmatrix.sync.aligned.m8n8.x4.shared.b16 {%0,%1,%2,%3}, [%4];"
        : "=r"(r[0]), "=r"(r[1]), "=r"(r[2]), "=r"(r[3]) : "r"(addr));
}
__device__ __forceinline__ void mma_f16(float* c, const uint32_t* a,
                                        uint32_t b0, uint32_t b1) {
    asm volatile(
        "mma.sync.aligned.m16n8k16.row.col.f32.f16.f16.f32 "
        "{%0,%1,%2,%3}, {%4,%5,%6,%7}, {%8,%9}, {%0,%1,%2,%3};"
        : "+f"(c[0]), "+f"(c[1]), "+f"(c[2]), "+f"(c[3])
        : "r"(a[0]), "r"(a[1]), "r"(a[2]), "r"(a[3]), "r"(b0), "r"(b1));
}

// unpack uint4 (8 fp16) to 8 floats
__device__ __forceinline__ void unpack8(uint4 u, float* f) {
    float2 v;
    v = __half22float2(*(__half2*)&u.x); f[0] = v.x; f[1] = v.y;
    v = __half22float2(((__half2*)&u.x)[1]); f[2] = v.x; f[3] = v.y;
    v = __half22float2(*(__half2*)&u.z); f[4] = v.x; f[5] = v.y;
    v = __half22float2(((__half2*)&u.z)[1]); f[6] = v.x; f[7] = v.y;
}

// fp16 row of 16 (32B = two uint4 loads) dotted with fp32 vector (fp32 accum)
__device__ __forceinline__ float dot16h(const __half* w, const float* s) {
    uint4 u0 = *(const uint4*)(w);
    uint4 u1 = *(const uint4*)(w + 8);
    float a[8], b[8];
    unpack8(u0, a); unpack8(u1, b);
    float d = 0.f;
#pragma unroll
    for (int i = 0; i < 8; i++) d += s[i] * a[i] + s[8 + i] * b[i];
    return d;
}

// fp16 row of 16 dotted with half2[8] vector, fp16 accumulation (fast path)
__device__ __forceinline__ float dot16hh(const __half* w, const __half2* s) {
    uint4 u0 = *(const uint4*)(w);
    uint4 u1 = *(const uint4*)(w + 8);
    const __half2* wh0 = (const __half2*)&u0;
    const __half2* wh1 = (const __half2*)&u1;
    __half2 acc = __hmul2(wh0[0], s[0]);
#pragma unroll
    for (int i = 1; i < 4; i++) acc = __hfma2(wh0[i], s[i], acc);
#pragma unroll
    for (int i = 0; i < 4; i++) acc = __hfma2(wh1[i], s[4 + i], acc);
    return __low2float(acc) + __high2float(acc);
}

// =================== fp16 GEMM via mma.sync (R12 config) ====================
#define ST_AH 0
#define ST_BH 16384
#define STAGE_SZ 32768
#define GEMM_SMEM (2 * STAGE_SZ)

__device__ __forceinline__ uint32_t sw_off(int row, int c) {
    return (uint32_t)((row << 7) + ((c ^ (row & 7)) << 4));
}

__device__ __forceinline__ void copy_arr(uint32_t dst, const __half* src,
                                         int ldk, int tid) {
#pragma unroll
    for (int it = 0; it < 4; it++) {
        int idx = tid + it * 256;
        int row = idx >> 3, c = idx & 7;
        cp16(dst + sw_off(row, c), src + (size_t)row * ldk + c * 8);
    }
}

__device__ __forceinline__ void ld_frag16(uint32_t arr, int baserow, int kstep,
                                          int lane, uint32_t* r) {
    int tile = lane >> 3, rin = lane & 7;
    int row = baserow + ((tile & 1) << 3) + rin;
    int chunk = (kstep << 1) + (tile >> 1);
    ldsm4(r, arr + sw_off(row, chunk));
}

// core GEMM body, shared by both entry points
__device__ __forceinline__ void gemm_body(const __half* gAh, const __half* gBh,
                                          float* C, int N, int K,
                                          int bm, int bn, char* smem) {
    uint32_t sb = smem_u32(smem);
    const int tid = threadIdx.x, lane = tid & 31, wid = tid >> 5;
    const int warp_m = (wid >> 2) * 64, warp_n = (wid & 3) * 32;
    const int niter = K / 64;

    float acc[4][4][4];
#pragma unroll
    for (int i = 0; i < 4; i++)
#pragma unroll
        for (int j = 0; j < 4; j++)
#pragma unroll
            for (int v = 0; v < 4; v++) acc[i][j][v] = 0.f;

    {
        uint32_t st = sb;
        copy_arr(st + ST_AH, gAh, K, tid);
        copy_arr(st + ST_BH, gBh, K, tid);
        CP_COMMIT();
    }

    for (int i = 0; i < niter; i++) {
        uint32_t st = sb + (uint32_t)(i & 1) * STAGE_SZ;
        if (i + 1 < niter) {
            uint32_t stn = sb + (uint32_t)((i + 1) & 1) * STAGE_SZ;
            int k0 = (i + 1) * 64;
            copy_arr(stn + ST_AH, gAh + k0, K, tid);
            copy_arr(stn + ST_BH, gBh + k0, K, tid);
            CP_COMMIT();
            CP_WAIT(1);
        } else {
            CP_WAIT(0);
        }
        __syncthreads();

#pragma unroll
        for (int ks = 0; ks < 4; ks++) {
            uint32_t ah[4][4], bh[2][4];
#pragma unroll
            for (int mt = 0; mt < 4; mt++)
                ld_frag16(st + ST_AH, warp_m + mt * 16, ks, lane, ah[mt]);
#pragma unroll
            for (int ng = 0; ng < 2; ng++)
                ld_frag16(st + ST_BH, warp_n + ng * 16, ks, lane, bh[ng]);
#pragma unroll
            for (int mt = 0; mt < 4; mt++) {
#pragma unroll
                for (int nt = 0; nt < 4; nt++) {
                    int ng = nt >> 1, p = nt & 1;
                    mma_f16(acc[mt][nt], ah[mt], bh[ng][p], bh[ng][2 + p]);
                }
            }
        }
        __syncthreads();
    }

#pragma unroll
    for (int mt = 0; mt < 4; mt++) {
        int row = bm + warp_m + mt * 16 + (lane >> 2);
#pragma unroll
        for (int nt = 0; nt < 4; nt++) {
            int col = bn + warp_n + nt * 8 + (lane & 3) * 2;
            float* p0 = C + (size_t)row * N + col;
            float* p1 = C + (size_t)(row + 8) * N + col;
            *(float2*)p0 = make_float2(acc[mt][nt][0], acc[mt][nt][1]);
            *(float2*)p1 = make_float2(acc[mt][nt][2], acc[mt][nt][3]);
        }
    }
}

// single GEMM
__global__ void __launch_bounds__(256, 2)
gemm_mma_f16(const __half* __restrict__ Ah, const __half* __restrict__ Bh,
             float* __restrict__ C, int M, int N, int K) {
    extern __shared__ char smem[];
    int bm = blockIdx.y * 128, bn = blockIdx.x * 128;
    gemm_body(Ah + (size_t)bm * K, Bh + (size_t)bn * K, C, N, K, bm, bn, smem);
}

// dual up-projection GEMM: blockIdx.z selects (W1 -> base1) or (W3 -> base3)
__global__ void __launch_bounds__(256, 2)
gemm_mma_f16_up(const __half* __restrict__ Ah,
                const __half* __restrict__ B1h, const __half* __restrict__ B3h,
                float* __restrict__ C1, float* __restrict__ C3,
                int N, int K) {
    extern __shared__ char smem[];
    const __half* Bh = blockIdx.z ? B3h : B1h;
    float* C = blockIdx.z ? C3 : C1;
    int bm = blockIdx.y * 128, bn = blockIdx.x * 128;
    gemm_body(Ah + (size_t)bm * K, Bh + (size_t)bn * K, C, N, K, bm, bn, smem);
}

// =================== fp32 -> fp16 conversions ===============================
__global__ void split1_kernel(const float* __restrict__ in,
                              __half* __restrict__ hi, int n4) {
    int i = blockIdx.x * blockDim.x + threadIdx.x;
    if (i >= n4) return;
    float4 v = *(const float4*)(in + (size_t)i * 4);
    __half* hp = hi + (size_t)i * 4;
    *(__half2*)(hp)     = __half2(__float2half(v.x), __float2half(v.y));
    *(__half2*)(hp + 2) = __half2(__float2half(v.z), __float2half(v.w));
}

// A2[e][r][f] -> a2t[e][f][r] fp16
__global__ void a2t_kernel(const float* __restrict__ A2) {
    int i = blockIdx.x * blockDim.x + threadIdx.x;
    if (i >= E_EXP * F_DIM * R_RANK) return;
    int r = i & (R_RANK - 1);
    int f = (i / R_RANK) % F_DIM;
    int e = i / (R_RANK * F_DIM);
    g_a2t[i] = __float2half(A2[((size_t)e * R_RANK + r) * F_DIM + f]);
}

// pack [A1 all experts | A3 all experts] -> g_lapk[256][D] fp16
// row n: n<128 -> A1[e=n>>4][r=n&15], else A3[(n-128)>>4][(n-128)&15]
__global__ void lapack_kernel(const float* __restrict__ A1,
                              const float* __restrict__ A3) {
    int i = blockIdx.x * blockDim.x + threadIdx.x;   // over LA_N * D / 4
    if (i >= LA_N * D_DIM / 4) return;
    int n = i / (D_DIM / 4);
    int d4 = i % (D_DIM / 4);
    const float* src = (n < 128)
        ? A1 + ((size_t)(n >> 4) * R_RANK + (n & 15)) * D_DIM
        : A3 + ((size_t)((n - 128) >> 4) * R_RANK + ((n - 128) & 15)) * D_DIM;
    float4 v = *(const float4*)(src + d4 * 4);
    __half* hp = g_lapk + (size_t)n * D_DIM + d4 * 4;
    *(__half2*)(hp)     = __half2(__float2half(v.x), __float2half(v.y));
    *(__half2*)(hp + 2) = __half2(__float2half(v.z), __float2half(v.w));
}

// ---------------- router ----------------------------------------------------
__global__ void router_kernel(const float* __restrict__ x,
                              const float* __restrict__ gw,
                              float* __restrict__ logits_out, int write_logits) {
    int t    = blockIdx.x * (blockDim.x >> 5) + (threadIdx.x >> 5);
    int lane = threadIdx.x & 31;
    if (t >= T_TOK) return;
    const float* h = x + (size_t)t * D_DIM;
    float acc[E_EXP];
#pragma unroll
    for (int e = 0; e < E_EXP; e++) acc[e] = 0.f;
    for (int d = lane * 4; d < D_DIM; d += 128) {
        float4 hv = *(const float4*)(h + d);
#pragma unroll
        for (int e = 0; e < E_EXP; e++) {
            float4 gv = *(const float4*)(gw + (size_t)e * D_DIM + d);
            acc[e] += hv.x * gv.x + hv.y * gv.y + hv.z * gv.z + hv.w * gv.w;
        }
    }
#pragma unroll
    for (int e = 0; e < E_EXP; e++) {
#pragma unroll
        for (int o = 16; o > 0; o >>= 1)
            acc[e] += __shfl_xor_sync(0xffffffffu, acc[e], o);
    }
    if (lane == 0) {
        if (write_logits) {
#pragma unroll
            for (int e = 0; e < E_EXP; e++)
                logits_out[(size_t)t * E_EXP + e] = acc[e];
        }
        float m = acc[0];
#pragma unroll
        for (int e = 1; e < E_EXP; e++) m = fmaxf(m, acc[e]);
        float p[E_EXP]; float s = 0.f;
#pragma unroll
        for (int e = 0; e < E_EXP; e++) { p[e] = expf(acc[e] - m); s += p[e]; }
        float invs = 1.f / s;
#pragma unroll
        for (int e = 0; e < E_EXP; e++) p[e] *= invs;
        int i0 = 0; float v0 = p[0];
#pragma unroll
        for (int e = 1; e < E_EXP; e++) if (p[e] > v0) { v0 = p[e]; i0 = e; }
        int i1 = -1; float v1 = -1.f;
#pragma unroll
        for (int e = 0; e < E_EXP; e++) {
            if (e == i0) continue;
            if (p[e] > v1) { v1 = p[e]; i1 = e; }
        }
        float inv = 1.f / (v0 + v1);
        g_sel [t * 2 + 0] = i0;  g_sel [t * 2 + 1] = i1;
        g_coef[t * 2 + 0] = v0 * inv;
        g_coef[t * 2 + 1] = v1 * inv;
    }
}

// ---------------- fused gate: 8 tokens/CTA, reads la from g_laall ------------
__global__ void __launch_bounds__(128)
gate_kernel() {
    const int t0 = blockIdx.x * GTOK;
    const int tid = threadIdx.x;
    const int lane = tid & 31, wid = tid >> 5;
    __shared__ __half2 s_la1h[GTOK][2][8];
    __shared__ __half2 s_la3h[GTOK][2][8];
    __shared__ float s_coef[GTOK][2];
    __shared__ int   s_sel [GTOK][2];
    __shared__ float s_la2w[4][GTOK][32];

    if (tid < GTOK * 2) {
        s_coef[tid >> 1][tid & 1] = g_coef[t0 * 2 + tid];
        s_sel [tid >> 1][tid & 1] = g_sel [t0 * 2 + tid];
    }
    for (int i = tid; i < 4 * GTOK * 32; i += 128)
        ((float*)s_la2w)[i] = 0.f;
    __syncthreads();

    // load la vectors from g_laall (sel-dependent columns)
    {
        int tt = tid >> 4, rest = tid & 15;
        int slot = rest >> 3, rp = rest & 7;
        const float* row = g_laall + (size_t)(t0 + tt) * LA_N;
        int e = s_sel[tt][slot];
        int c1 = e * 16 + rp * 2;         // la1 block: cols [0,128)
        int c3 = 128 + e * 16 + rp * 2;   // la3 block: cols [128,256)
        s_la1h[tt][slot][rp] = __floats2half2_rn(row[c1], row[c1 + 1]);
        s_la3h[tt][slot][rp] = __floats2half2_rn(row[c3], row[c3 + 1]);
    }
    __syncthreads();

    const int rsel = lane & 15;
    for (int c0 = 0; c0 < F_DIM; c0 += 128) {
        const int f = c0 + tid;
        const int fbase = c0 + wid * 32;
#pragma unroll 1
        for (int tt = 0; tt < GTOK; tt++) {
            const int t = t0 + tt;
            const int e0 = s_sel[tt][0], e1 = s_sel[tt][1];
            const float cc0 = s_coef[tt][0], cc1 = s_coef[tt][1];
            float b1v = g_base1[(size_t)t * F_DIM + f];
            float b3v = g_base3[(size_t)t * F_DIM + f];
            float d10 = dot16hh(g_b1h + ((size_t)e0 * F_DIM + f) * R_RANK, s_la1h[tt][0]);
            float d11 = dot16hh(g_b1h + ((size_t)e1 * F_DIM + f) * R_RANK, s_la1h[tt][1]);
            float d30 = dot16hh(g_b3h + ((size_t)e0 * F_DIM + f) * R_RANK, s_la3h[tt][0]);
            float d31 = dot16hh(g_b3h + ((size_t)e1 * F_DIM + f) * R_RANK, s_la3h[tt][1]);
            float u10 = b1v + d10, u30 = b3v + d30;
            float u11 = b1v + d11, u31 = b3v + d31;
            float g0 = (u10 / (1.f + expf(-u10))) * u30;
            float g1 = (u11 / (1.f + expf(-u11))) * u31;
            g_gch[(size_t)t * F_DIM + f] = __float2half(cc0 * g0 + cc1 * g1);
            const int eM = (lane < 16) ? e0 : e1;
            const __half* arow = g_a2t + (size_t)eM * F_DIM * R_RANK + rsel;
            float p = 0.f;
#pragma unroll
            for (int s = 0; s < 32; s++) {
                float g0b = __shfl_sync(0xffffffffu, g0, s);
                float g1b = __shfl_sync(0xffffffffu, g1, s);
                float gb = (lane < 16) ? g0b : g1b;
                float av = __half2float(arow[(size_t)(fbase + s) * R_RANK]);
                p += gb * av;
            }
            s_la2w[wid][tt][lane] += p;
        }
    }
    __syncthreads();
    for (int i = tid; i < GTOK * 32; i += 128) {
        int tt = i >> 5, q = i & 31;
        float v = s_la2w[0][tt][q] + s_la2w[1][tt][q] + s_la2w[2][tt][q] + s_la2w[3][tt][q];
        float c = (q < 16) ? s_coef[tt][0] : s_coef[tt][1];
        g_la2c[(t0 + tt) * 32 + q] = v * c;
    }
}

// ---------------- out += sum_k la2c[p_k] @ B2[e_k]^T (fp16 B2, 16B loads) ----
__global__ void lora2_out_kernel(float* __restrict__ out) {
    int t   = blockIdx.x;
    int tid = threadIdx.x;
    __shared__ float s_l2[32];
    if (tid < 32) s_l2[tid] = g_la2c[t * 32 + tid];
    __syncthreads();
    int e0 = g_sel[t * 2], e1 = g_sel[t * 2 + 1];
    const __half* b2e0 = g_b2h + (size_t)e0 * D_DIM * R_RANK;
    const __half* b2e1 = g_b2h + (size_t)e1 * D_DIM * R_RANK;
    for (int d = tid; d < D_DIM; d += 256) {
        float s = dot16h(b2e0 + (size_t)d * R_RANK, s_l2)
                + dot16h(b2e1 + (size_t)d * R_RANK, s_l2 + 16);
        out[(size_t)t * D_DIM + d] += s;
    }
}

// ---------------- launch ----------------------------------------------------
extern "C" void kernel_launch(void* const* d_in, const int* in_sizes, int n_in,
                              void* d_out, int out_size) {
    (void)in_sizes; (void)n_in;
    const float* x  = (const float*)d_in[0];
    const float* gw = (const float*)d_in[1];
    const float* W1 = (const float*)d_in[2];
    const float* W3 = (const float*)d_in[3];
    const float* W2 = (const float*)d_in[4];
    const float* A1 = (const float*)d_in[5];
    const float* B1 = (const float*)d_in[6];
    const float* A3 = (const float*)d_in[7];
    const float* B3 = (const float*)d_in[8];
    const float* A2 = (const float*)d_in[9];
    const float* B2 = (const float*)d_in[10];
    float* out = (float*)d_out;

    int write_logits = (out_size >= T_TOK * D_DIM + T_TOK * E_EXP) ? 1 : 0;
    float* logits = out + (size_t)T_TOK * D_DIM;

    float *base1, *base3, *laall;
    __half *xh, *w1h, *w3h, *w2h, *gch, *lapk;
    __half *b1h, *b3h, *b2h;
    cudaGetSymbolAddress((void**)&base1, g_base1);
    cudaGetSymbolAddress((void**)&base3, g_base3);
    cudaGetSymbolAddress((void**)&laall, g_laall);
    cudaGetSymbolAddress((void**)&xh,   g_xh);
    cudaGetSymbolAddress((void**)&w1h,  g_w1h);
    cudaGetSymbolAddress((void**)&w3h,  g_w3h);
    cudaGetSymbolAddress((void**)&w2h,  g_w2h);
    cudaGetSymbolAddress((void**)&gch,  g_gch);
    cudaGetSymbolAddress((void**)&lapk, g_lapk);
    cudaGetSymbolAddress((void**)&b1h,  g_b1h);
    cudaGetSymbolAddress((void**)&b3h,  g_b3h);
    cudaGetSymbolAddress((void**)&b2h,  g_b2h);

    cudaFuncSetAttribute(gemm_mma_f16,
                         cudaFuncAttributeMaxDynamicSharedMemorySize, GEMM_SMEM);
    cudaFuncSetAttribute(gemm_mma_f16_up,
                         cudaFuncAttributeMaxDynamicSharedMemorySize, GEMM_SMEM);

    // 1. routing (writes router_logits output)
    router_kernel<<<T_TOK / 8, 256>>>(x, gw, logits, write_logits);

    // 2. fp16 conversions + packs
    {
        int n4;
        n4 = T_TOK * D_DIM / 4;          split1_kernel<<<(n4 + 255) / 256, 256>>>(x,  xh,  n4);
        n4 = F_DIM * D_DIM / 4;          split1_kernel<<<(n4 + 255) / 256, 256>>>(W1, w1h, n4);
        n4 = F_DIM * D_DIM / 4;          split1_kernel<<<(n4 + 255) / 256, 256>>>(W3, w3h, n4);
        n4 = D_DIM * F_DIM / 4;          split1_kernel<<<(n4 + 255) / 256, 256>>>(W2, w2h, n4);
        n4 = E_EXP * F_DIM * R_RANK / 4; split1_kernel<<<(n4 + 255) / 256, 256>>>(B1, b1h, n4);
        n4 = E_EXP * F_DIM * R_RANK / 4; split1_kernel<<<(n4 + 255) / 256, 256>>>(B3, b3h, n4);
        n4 = E_EXP * D_DIM * R_RANK / 4; split1_kernel<<<(n4 + 255) / 256, 256>>>(B2, b2h, n4);
        int nt = E_EXP * F_DIM * R_RANK;
        a2t_kernel<<<(nt + 255) / 256, 256>>>(A2);
        int np = LA_N * D_DIM / 4;
        lapack_kernel<<<(np + 255) / 256, 256>>>(A1, A3);
    }

    // 3. lora-A projections for ALL experts via tensor-core GEMM
    {
        dim3 gLa(LA_N / 128, T_TOK / 128);
        gemm_mma_f16<<<gLa, 256, GEMM_SMEM>>>(xh, lapk, laall, T_TOK, LA_N, D_DIM);
    }

    // 4. base projections: one merged launch (z = 0: W1->base1, z = 1: W3->base3)
    {
        dim3 gUp(F_DIM / 128, T_TOK / 128, 2);
        gemm_mma_f16_up<<<gUp, 256, GEMM_SMEM>>>(xh, w1h, w3h, base1, base3,
                                                 F_DIM, D_DIM);
    }

    // 5. fused SwiGLU gate (token-grouped) + combine + g@A2^T
    gate_kernel<<<T_TOK / GTOK, 128>>>();

    // 6. down projection: out = gc @ W2^T
    {
        dim3 gDn(D_DIM / 128, T_TOK / 128);
        gemm_mma_f16<<<gDn, 256, GEMM_SMEM>>>(gch, w2h, out, T_TOK, D_DIM, F_DIM);
    }

    // 7. rank-16 lora-2 epilogue
    lora2_out_kernel<<<T_TOK, 256>>>(out);
}